// round 7
// baseline (speedup 1.0000x reference)
#include <cuda_runtime.h>
#include <cuda_bf16.h>
#include <math.h>
#include <stdint.h>

#define FEAT_I 512
#define H_DIM  1024
#define CODE   640
#define CODE_G 320
#define FEAT_G 256
#define B_     8
#define T_     4096
#define N_     (B_ * T_)                  // 32768
#define Q_ELEMS ((size_t)B_ * 512 * T_)   // 16,777,216

#define K3_1 (3 * FEAT_I)    // 1536
#define K3_2 (3 * H_DIM)     // 3072

// dynamic smem: 2 bufs x (3 A-planes + 3 B-planes) x 16KB = 192KB
#define BUF_STRIDE 98304
#define B_OFF      49152
#define SMEM_DYN   196608

// ---------------------------------------------------------------------------
// Device scratch (allocation-free rule)
// ---------------------------------------------------------------------------
__device__ __nv_bfloat16 g_xb [(size_t)N_    * K3_1];  // x planes   [m][p*512+k]
__device__ __nv_bfloat16 g_w1b[(size_t)H_DIM * K3_1];  // W1^T planes[n][p*512+k]
__device__ __nv_bfloat16 g_hb [(size_t)N_    * K3_2];  // h planes   [m][p*1024+k]
__device__ __nv_bfloat16 g_w2b[(size_t)CODE  * K3_2];  // W2^T planes[n][p*1024+k]
__device__ float         g_logits[(size_t)N_ * CODE];  // perturbed logits

// ---------------------------------------------------------------------------
// PTX helpers (arch-agnostic sm_80-class)
// ---------------------------------------------------------------------------
__device__ __forceinline__ uint32_t smem_u32(const void* p) {
    uint32_t a;
    asm("{ .reg .u64 t; cvta.to.shared.u64 t, %1; cvt.u32.u64 %0, t; }" : "=r"(a) : "l"(p));
    return a;
}
__device__ __forceinline__ void cp16(uint32_t saddr, const void* g) {
    asm volatile("cp.async.cg.shared.global [%0], [%1], 16;" :: "r"(saddr), "l"(g));
}
#define CP_COMMIT() asm volatile("cp.async.commit_group;" ::: "memory")
#define CP_WAIT0()  asm volatile("cp.async.wait_group 0;" ::: "memory")
#define CP_WAIT1()  asm volatile("cp.async.wait_group 1;" ::: "memory")

__device__ __forceinline__ void ldsm4(uint32_t& a, uint32_t& b, uint32_t& c, uint32_t& d,
                                      uint32_t addr) {
    asm volatile("ldmatrix.sync.aligned.m8n8.x4.shared.b16 {%0,%1,%2,%3}, [%4];"
                 : "=r"(a), "=r"(b), "=r"(c), "=r"(d) : "r"(addr));
}
__device__ __forceinline__ void mma16816(float* d, const uint32_t* a, uint32_t b0, uint32_t b1) {
    asm volatile("mma.sync.aligned.m16n8k16.row.col.f32.bf16.bf16.f32 "
                 "{%0,%1,%2,%3},{%4,%5,%6,%7},{%8,%9},{%0,%1,%2,%3};"
                 : "+f"(d[0]), "+f"(d[1]), "+f"(d[2]), "+f"(d[3])
                 : "r"(a[0]), "r"(a[1]), "r"(a[2]), "r"(a[3]), "r"(b0), "r"(b1));
}

__device__ __forceinline__ void split3(float v, __nv_bfloat16& a, __nv_bfloat16& b,
                                       __nv_bfloat16& c) {
    a = __float2bfloat16(v);
    float r = v - __bfloat162float(a);
    b = __float2bfloat16(r);
    float r2 = r - __bfloat162float(b);
    c = __float2bfloat16(r2);
}

// ---------------------------------------------------------------------------
// Core: 128x128 block. Super-chunk = 64 k-columns of ALL 6 planes (96KB).
// Per k16 step: 18 ldmatrix.x4 feed 96 HMMAs (fragments reused across pairs).
// 2-ahead cp.async pipeline (wait_group 1).
// ---------------------------------------------------------------------------
template<int KPLANE>
__device__ __forceinline__ void gemm_core(const char* __restrict__ Abase,
                                          const char* __restrict__ Bbase,
                                          int tid, uint32_t smb,
                                          float acc[4][4][4]) {
    const int lane = tid & 31, wid = tid >> 5;
    const int warp_m = wid >> 2;     // 0..1
    const int warp_n = wid & 3;      // 0..3
    const int r0 = tid >> 3, cc = tid & 7;
    constexpr int KCH = KPLANE / 64;
    const size_t ROWB = (size_t)KPLANE * 6;   // 3 planes * 2 bytes

    auto issue = [&](int kc, int buf) {
        const uint32_t base = smb + buf * BUF_STRIDE;
#pragma unroll
        for (int p = 0; p < 3; p++) {
            const size_t col = (size_t)(p * KPLANE + kc * 64) * 2 + cc * 16;
#pragma unroll
            for (int i = 0; i < 4; i++) {
                const int r = r0 + 32 * i;
                const uint32_t so = (uint32_t)(r * 128 + ((cc ^ (r & 7)) * 16));
                cp16(base + p * 16384 + so,         Abase + (size_t)r * ROWB + col);
                cp16(base + B_OFF + p * 16384 + so, Bbase + (size_t)r * ROWB + col);
            }
        }
    };

    issue(0, 0); CP_COMMIT();
    issue(1, 1); CP_COMMIT();

    for (int kc = 0; kc < KCH; kc++) {
        if (kc == KCH - 1) { CP_WAIT0(); } else { CP_WAIT1(); }
        __syncthreads();
        const uint32_t bufb = smb + (kc & 1) * BUF_STRIDE;
#pragma unroll
        for (int kk = 0; kk < 4; kk++) {
            const int lrow = lane & 15;
            const int ch = kk * 2 + (lane >> 4);
            uint32_t afr[3][4][4], bfr[3][2][4];
#pragma unroll
            for (int p = 0; p < 3; p++) {
                const uint32_t bA = bufb + p * 16384;
                const uint32_t bB = bA + B_OFF;
#pragma unroll
                for (int im = 0; im < 4; im++) {
                    const int r = warp_m * 64 + im * 16 + lrow;
                    ldsm4(afr[p][im][0], afr[p][im][1], afr[p][im][2], afr[p][im][3],
                          bA + r * 128 + ((ch ^ (r & 7)) * 16));
                }
#pragma unroll
                for (int i2 = 0; i2 < 2; i2++) {
                    const int r = warp_n * 32 + i2 * 16 + lrow;
                    ldsm4(bfr[p][i2][0], bfr[p][i2][1], bfr[p][i2][2], bfr[p][i2][3],
                          bB + r * 128 + ((ch ^ (r & 7)) * 16));
                }
            }
#pragma unroll
            for (int t = 0; t < 6; t++) {
                constexpr int pa_[6] = {0, 1, 0, 2, 0, 1};
                constexpr int pb_[6] = {0, 0, 1, 0, 2, 1};
                const int pa = pa_[t], pb = pb_[t];
#pragma unroll
                for (int im = 0; im < 4; im++)
#pragma unroll
                    for (int in = 0; in < 4; in++)
                        mma16816(acc[im][in], afr[pa][im],
                                 bfr[pb][in >> 1][in & 1], bfr[pb][in >> 1][(in & 1) + 2]);
            }
        }
        __syncthreads();
        if (kc + 2 < KCH) { issue(kc + 2, kc & 1); CP_COMMIT(); }
    }
    __syncthreads();
}

// ---------------------------------------------------------------------------
// GEMM1: h = relu(x@W1 + b1) -> split3 -> g_hb (coalesced via smem staging)
// ---------------------------------------------------------------------------
__global__ __launch_bounds__(256, 1)
void gemm1_mma(const float* __restrict__ b1) {
    extern __shared__ char smem[];
    const uint32_t smb = smem_u32(smem);
    const int tid = threadIdx.x, lane = tid & 31, wid = tid >> 5;
    const int warp_m = wid >> 2, warp_n = wid & 3;
    const int jBase = blockIdx.x * 128;
    const int mBase = blockIdx.y * 128;

    float acc[4][4][4];
#pragma unroll
    for (int i = 0; i < 4; i++)
#pragma unroll
        for (int j = 0; j < 4; j++)
#pragma unroll
            for (int k = 0; k < 4; k++) acc[i][j][k] = 0.f;

    gemm_core<FEAT_I>((const char*)(g_xb + (size_t)mBase * K3_1),
                      (const char*)(g_w1b + (size_t)jBase * K3_1), tid, smb, acc);

    // bias + relu in place
    float bv[4][2];
#pragma unroll
    for (int in = 0; in < 4; in++)
#pragma unroll
        for (int e = 0; e < 2; e++)
            bv[in][e] = __ldg(&b1[jBase + warp_n * 32 + in * 8 + (lane & 3) * 2 + e]);
#pragma unroll
    for (int im = 0; im < 4; im++)
#pragma unroll
        for (int in = 0; in < 4; in++)
#pragma unroll
            for (int q = 0; q < 4; q++) {
                float z = acc[im][in][q] + bv[in][q & 1];
                acc[im][in][q] = z > 0.f ? z : 0.f;
            }

    // 3 planes: peel bf16, stage in smem [128][128] bf16, coalesced copy-out
    __nv_bfloat16* stage = (__nv_bfloat16*)smem;
#pragma unroll
    for (int p = 0; p < 3; p++) {
#pragma unroll
        for (int im = 0; im < 4; im++)
#pragma unroll
            for (int in = 0; in < 4; in++)
#pragma unroll
                for (int rr = 0; rr < 2; rr++) {
                    const int r = warp_m * 64 + im * 16 + (lane >> 2) + rr * 8;
                    const int col = warp_n * 32 + in * 8 + (lane & 3) * 2;
                    __nv_bfloat162 v;
#pragma unroll
                    for (int e = 0; e < 2; e++) {
                        float z = acc[im][in][rr * 2 + e];
                        __nv_bfloat16 hp = __float2bfloat16(z);
                        acc[im][in][rr * 2 + e] = z - __bfloat162float(hp);
                        ((__nv_bfloat16*)&v)[e] = hp;
                    }
                    *(__nv_bfloat162*)&stage[r * 128 + col] = v;
                }
        __syncthreads();
#pragma unroll
        for (int i = 0; i < 8; i++) {
            const int id = tid + 256 * i;          // 2048 float4
            const int r = id >> 4, c4 = id & 15;
            float4 v = *(const float4*)&stage[r * 128 + c4 * 8];
            *(float4*)&g_hb[(size_t)(mBase + r) * K3_2 + p * H_DIM + jBase + c4 * 8] = v;
        }
        __syncthreads();
    }
}

// ---------------------------------------------------------------------------
// GEMM2: logits = h@W2 + b2 + gumbel -> g_logits (fp32)
// ---------------------------------------------------------------------------
__global__ __launch_bounds__(256, 1)
void gemm2_mma(const float* __restrict__ b2, const float* __restrict__ gumbel_u) {
    extern __shared__ char smem[];
    const uint32_t smb = smem_u32(smem);
    const int tid = threadIdx.x, lane = tid & 31, wid = tid >> 5;
    const int warp_m = wid >> 2, warp_n = wid & 3;
    const int jBase = blockIdx.x * 128;
    const int mBase = blockIdx.y * 128;

    float acc[4][4][4];
#pragma unroll
    for (int i = 0; i < 4; i++)
#pragma unroll
        for (int j = 0; j < 4; j++)
#pragma unroll
            for (int k = 0; k < 4; k++) acc[i][j][k] = 0.f;

    gemm_core<H_DIM>((const char*)(g_hb + (size_t)mBase * K3_2),
                     (const char*)(g_w2b + (size_t)jBase * K3_2), tid, smb, acc);

    float bv[4][2];
#pragma unroll
    for (int in = 0; in < 4; in++)
#pragma unroll
        for (int e = 0; e < 2; e++)
            bv[in][e] = __ldg(&b2[jBase + warp_n * 32 + in * 8 + (lane & 3) * 2 + e]);

#pragma unroll
    for (int im = 0; im < 4; im++)
#pragma unroll
        for (int in = 0; in < 4; in++)
#pragma unroll
            for (int rr = 0; rr < 2; rr++) {
                const int m = mBase + warp_m * 64 + im * 16 + (lane >> 2) + rr * 8;
                const int j = jBase + warp_n * 32 + in * 8 + (lane & 3) * 2;
                const float2 u = *(const float2*)&gumbel_u[(size_t)m * CODE + j];
                float2 o;
                o.x = acc[im][in][rr * 2 + 0] + bv[in][0]
                      - logf(-logf(u.x + 1e-10f) + 1e-10f);
                o.y = acc[im][in][rr * 2 + 1] + bv[in][1]
                      - logf(-logf(u.y + 1e-10f) + 1e-10f);
                *(float2*)&g_logits[(size_t)m * CODE + j] = o;
            }
}

// ---------------------------------------------------------------------------
// Conversion kernels (tiled transpose + 3-plane split)
// ---------------------------------------------------------------------------
__global__ __launch_bounds__(256)
void conv_x_kernel(const float* __restrict__ series) {
    __shared__ float s[32][33];
    const int k0 = blockIdx.x * 32, t0 = blockIdx.y * 32, b = blockIdx.z;
    const int tx = threadIdx.x, ty = threadIdx.y;
#pragma unroll
    for (int i = 0; i < 4; i++) {
        int kk = ty + 8 * i;
        s[kk][tx] = series[((size_t)b * FEAT_I + k0 + kk) * T_ + t0 + tx];
    }
    __syncthreads();
#pragma unroll
    for (int i = 0; i < 4; i++) {
        int tt = ty + 8 * i;
        int m = b * T_ + t0 + tt;
        float v = s[tx][tt];
        __nv_bfloat16 h, md, l;
        split3(v, h, md, l);
        __nv_bfloat16* row = g_xb + (size_t)m * K3_1;
        row[0 * FEAT_I + k0 + tx] = h;
        row[1 * FEAT_I + k0 + tx] = md;
        row[2 * FEAT_I + k0 + tx] = l;
    }
}

__global__ __launch_bounds__(256)
void conv_w1_kernel(const float* __restrict__ W1) {
    __shared__ float s[32][33];
    const int k0 = blockIdx.x * 32, n0 = blockIdx.y * 32;
    const int tx = threadIdx.x, ty = threadIdx.y;
#pragma unroll
    for (int i = 0; i < 4; i++) {
        int kk = ty + 8 * i;
        s[kk][tx] = W1[(size_t)(k0 + kk) * H_DIM + n0 + tx];
    }
    __syncthreads();
#pragma unroll
    for (int i = 0; i < 4; i++) {
        int nn = ty + 8 * i;
        float v = s[tx][nn];
        __nv_bfloat16 h, md, l;
        split3(v, h, md, l);
        __nv_bfloat16* row = g_w1b + (size_t)(n0 + nn) * K3_1;
        row[0 * FEAT_I + k0 + tx] = h;
        row[1 * FEAT_I + k0 + tx] = md;
        row[2 * FEAT_I + k0 + tx] = l;
    }
}

__global__ __launch_bounds__(256)
void conv_w2_kernel(const float* __restrict__ W2) {
    __shared__ float s[32][33];
    const int k0 = blockIdx.x * 32, n0 = blockIdx.y * 32;
    const int tx = threadIdx.x, ty = threadIdx.y;
#pragma unroll
    for (int i = 0; i < 4; i++) {
        int kk = ty + 8 * i;
        s[kk][tx] = W2[(size_t)(k0 + kk) * CODE + n0 + tx];
    }
    __syncthreads();
#pragma unroll
    for (int i = 0; i < 4; i++) {
        int nn = ty + 8 * i;
        float v = s[tx][nn];
        __nv_bfloat16 h, md, l;
        split3(v, h, md, l);
        __nv_bfloat16* row = g_w2b + (size_t)(n0 + nn) * K3_2;
        row[0 * H_DIM + k0 + tx] = h;
        row[1 * H_DIM + k0 + tx] = md;
        row[2 * H_DIM + k0 + tx] = l;
    }
}

// ---------------------------------------------------------------------------
// Argmax over 320 perturbed logits per (n,g) + codebook gather (t-coalesced)
// ---------------------------------------------------------------------------
__global__ __launch_bounds__(256)
void argmax_gather_kernel(const float* __restrict__ codebook,
                          float* __restrict__ out)
{
    const int t0 = blockIdx.x * 32;
    const int b  = blockIdx.y;
    const int g  = blockIdx.z;

    __shared__ int s_idx[32];

    const int tid  = threadIdx.x;
    const int lane = tid & 31;
    const int w    = tid >> 5;

#pragma unroll
    for (int rr = 0; rr < 4; rr++) {
        const int tl = w * 4 + rr;
        const int n  = b * T_ + t0 + tl;
        const float* lp = g_logits + (size_t)n * CODE + g * CODE_G;
        float best = -INFINITY;
        int   bi   = 0;
        for (int c = lane; c < CODE_G; c += 32) {
            float v = lp[c];
            if (v > best) { best = v; bi = c; }
        }
#pragma unroll
        for (int off = 16; off; off >>= 1) {
            float ov = __shfl_down_sync(0xffffffffu, best, off);
            int   oi = __shfl_down_sync(0xffffffffu, bi,   off);
            if (ov > best || (ov == best && oi < bi)) { best = ov; bi = oi; }
        }
        if (lane == 0) {
            s_idx[tl] = bi;
            out[Q_ELEMS + (size_t)n * 2 + g] = (float)bi;
        }
    }
    __syncthreads();

    const int tx  = tid & 31;
    const int fy  = tid >> 5;
    const int idx = s_idx[tx];
    const float* cbrow = codebook + ((size_t)g * CODE_G + idx) * FEAT_G;
    float* outb = out + ((size_t)b * 512 + g * FEAT_G) * T_ + t0;
    for (int f = fy; f < FEAT_G; f += 8)
        outb[(size_t)f * T_ + tx] = cbrow[f];
}

// ---------------------------------------------------------------------------
extern "C" void kernel_launch(void* const* d_in, const int* in_sizes, int n_in,
                              void* d_out, int out_size)
{
    const float* series   = (const float*)d_in[0];
    const float* gumbel_u = (const float*)d_in[1];
    const float* W1       = (const float*)d_in[2];
    const float* b1       = (const float*)d_in[3];
    const float* W2       = (const float*)d_in[4];
    const float* b2       = (const float*)d_in[5];
    const float* codebook = (const float*)d_in[6];
    float* out = (float*)d_out;

    cudaFuncSetAttribute(gemm1_mma, cudaFuncAttributeMaxDynamicSharedMemorySize, SMEM_DYN);
    cudaFuncSetAttribute(gemm2_mma, cudaFuncAttributeMaxDynamicSharedMemorySize, SMEM_DYN);

    conv_x_kernel <<<dim3(FEAT_I / 32, T_ / 32, B_), dim3(32, 8)>>>(series);
    conv_w1_kernel<<<dim3(FEAT_I / 32, H_DIM / 32),  dim3(32, 8)>>>(W1);
    conv_w2_kernel<<<dim3(H_DIM / 32, CODE / 32),    dim3(32, 8)>>>(W2);

    gemm1_mma<<<dim3(H_DIM / 128, N_ / 128), 256, SMEM_DYN>>>(b1);
    gemm2_mma<<<dim3(CODE / 128,  N_ / 128), 256, SMEM_DYN>>>(b2, gumbel_u);

    argmax_gather_kernel<<<dim3(T_ / 32, B_, 2), 256>>>(codebook, out);
}

// round 9
// speedup vs baseline: 1.0389x; 1.0389x over previous
#include <cuda_runtime.h>
#include <cuda_bf16.h>
#include <math.h>
#include <stdint.h>

#define FEAT_I 512
#define H_DIM  1024
#define CODE   640
#define CODE_G 320
#define FEAT_G 256
#define B_     8
#define T_     4096
#define N_     (B_ * T_)                  // 32768
#define Q_ELEMS ((size_t)B_ * 512 * T_)   // 16,777,216

#define K3_1 (3 * FEAT_I)    // 1536
#define K3_2 (3 * H_DIM)     // 3072

// dynamic smem: 2 bufs x (3 A-planes + 3 B-planes) x 8KB = 96KB per CTA
#define PLANE_SZ   8192
#define B_OFF      24576
#define BUF_STRIDE 49152
#define SMEM_DYN   98304

// ---------------------------------------------------------------------------
// Device scratch (allocation-free rule)
// ---------------------------------------------------------------------------
__device__ __nv_bfloat16 g_xb [(size_t)N_    * K3_1];  // x planes   [m][p*512+k]
__device__ __nv_bfloat16 g_w1b[(size_t)H_DIM * K3_1];  // W1^T planes[n][p*512+k]
__device__ __nv_bfloat16 g_hb [(size_t)N_    * K3_2];  // h planes   [m][p*1024+k]
__device__ __nv_bfloat16 g_w2b[(size_t)CODE  * K3_2];  // W2^T planes[n][p*1024+k]
__device__ float         g_logits[(size_t)N_ * CODE];  // perturbed logits

// ---------------------------------------------------------------------------
// PTX helpers (arch-agnostic sm_80-class)
// ---------------------------------------------------------------------------
__device__ __forceinline__ uint32_t smem_u32(const void* p) {
    uint32_t a;
    asm("{ .reg .u64 t; cvta.to.shared.u64 t, %1; cvt.u32.u64 %0, t; }" : "=r"(a) : "l"(p));
    return a;
}
__device__ __forceinline__ void cp16(uint32_t saddr, const void* g) {
    asm volatile("cp.async.cg.shared.global [%0], [%1], 16;" :: "r"(saddr), "l"(g));
}
#define CP_COMMIT() asm volatile("cp.async.commit_group;" ::: "memory")
#define CP_WAIT0()  asm volatile("cp.async.wait_group 0;" ::: "memory")
#define CP_WAIT1()  asm volatile("cp.async.wait_group 1;" ::: "memory")

__device__ __forceinline__ void ldsm4(uint32_t& a, uint32_t& b, uint32_t& c, uint32_t& d,
                                      uint32_t addr) {
    asm volatile("ldmatrix.sync.aligned.m8n8.x4.shared.b16 {%0,%1,%2,%3}, [%4];"
                 : "=r"(a), "=r"(b), "=r"(c), "=r"(d) : "r"(addr));
}
__device__ __forceinline__ void mma16816(float* d, const uint32_t* a, uint32_t b0, uint32_t b1) {
    asm volatile("mma.sync.aligned.m16n8k16.row.col.f32.bf16.bf16.f32 "
                 "{%0,%1,%2,%3},{%4,%5,%6,%7},{%8,%9},{%0,%1,%2,%3};"
                 : "+f"(d[0]), "+f"(d[1]), "+f"(d[2]), "+f"(d[3])
                 : "r"(a[0]), "r"(a[1]), "r"(a[2]), "r"(a[3]), "r"(b0), "r"(b1));
}

__device__ __forceinline__ void split3(float v, __nv_bfloat16& a, __nv_bfloat16& b,
                                       __nv_bfloat16& c) {
    a = __float2bfloat16(v);
    float r = v - __bfloat162float(a);
    b = __float2bfloat16(r);
    float r2 = r - __bfloat162float(b);
    c = __float2bfloat16(r2);
}

// swizzled byte offset within one 128x64B plane
__device__ __forceinline__ uint32_t plane_swz(int r, int c) {
    return (uint32_t)(r * 64 + ((c ^ ((r >> 1) & 3)) * 16));
}

// ---------------------------------------------------------------------------
// Core: 128x128 block. Super-chunk = 32 k-columns of ALL 6 planes (48KB).
// A-plane-outer term order -> only 1 A-frag set + 1 B-frag set live (fits
// 128 regs => 2 CTAs/SM). 24 ldmatrix.x4 feed 96 HMMAs per k16 step.
// ---------------------------------------------------------------------------
template<int KPLANE>
__device__ __forceinline__ void gemm_core(const char* __restrict__ Abase,
                                          const char* __restrict__ Bbase,
                                          int tid, uint32_t smb,
                                          float acc[4][4][4]) {
    const int lane = tid & 31, wid = tid >> 5;
    const int warp_m = wid >> 2;     // 0..1
    const int warp_n = wid & 3;      // 0..3
    constexpr int KCH = KPLANE / 32;
    const size_t ROWB = (size_t)KPLANE * 6;   // 3 planes * 2 bytes

    const int cst = tid & 3;         // 16B chunk for stores
    const int rst = tid >> 2;        // 0..63

    auto issue = [&](int kc, int buf) {
        const uint32_t base = smb + buf * BUF_STRIDE;
#pragma unroll
        for (int p = 0; p < 3; p++) {
            const size_t col = (size_t)(p * KPLANE + kc * 32) * 2 + cst * 16;
#pragma unroll
            for (int i = 0; i < 2; i++) {
                const int r = rst + 64 * i;
                const uint32_t so = plane_swz(r, cst);
                cp16(base + p * PLANE_SZ + so,         Abase + (size_t)r * ROWB + col);
                cp16(base + B_OFF + p * PLANE_SZ + so, Bbase + (size_t)r * ROWB + col);
            }
        }
    };

    issue(0, 0); CP_COMMIT();
    issue(1, 1); CP_COMMIT();

    for (int kc = 0; kc < KCH; kc++) {
        if (kc == KCH - 1) { CP_WAIT0(); } else { CP_WAIT1(); }
        __syncthreads();
        const uint32_t bufb = smb + (kc & 1) * BUF_STRIDE;
#pragma unroll
        for (int kk = 0; kk < 2; kk++) {
            const int lrow = lane & 15;
            const int ch = kk * 2 + (lane >> 4);
            uint32_t afr[4][4], bfr[2][4];

            auto loadA = [&](int pa) {
                const uint32_t bA = bufb + pa * PLANE_SZ;
#pragma unroll
                for (int im = 0; im < 4; im++) {
                    const int r = warp_m * 64 + im * 16 + lrow;
                    ldsm4(afr[im][0], afr[im][1], afr[im][2], afr[im][3],
                          bA + plane_swz(r, ch));
                }
            };
            auto loadB = [&](int pb) {
                const uint32_t bB = bufb + B_OFF + pb * PLANE_SZ;
#pragma unroll
                for (int i2 = 0; i2 < 2; i2++) {
                    const int r = warp_n * 32 + i2 * 16 + lrow;
                    ldsm4(bfr[i2][0], bfr[i2][1], bfr[i2][2], bfr[i2][3],
                          bB + plane_swz(r, ch));
                }
            };
            auto mmas = [&]() {
#pragma unroll
                for (int im = 0; im < 4; im++)
#pragma unroll
                    for (int in = 0; in < 4; in++)
                        mma16816(acc[im][in], afr[im],
                                 bfr[in >> 1][in & 1], bfr[in >> 1][(in & 1) + 2]);
            };

            loadA(0); loadB(0); mmas(); loadB(1); mmas(); loadB(2); mmas();
            loadA(1); loadB(0); mmas(); loadB(1); mmas();
            loadA(2); loadB(0); mmas();
        }
        __syncthreads();
        if (kc + 2 < KCH) { issue(kc + 2, kc & 1); CP_COMMIT(); }
    }
    __syncthreads();
}

// ---------------------------------------------------------------------------
// GEMM1: h = relu(x@W1 + b1) -> split3 -> g_hb (coalesced via smem staging)
// ---------------------------------------------------------------------------
__global__ __launch_bounds__(256, 2)
void gemm1_mma(const float* __restrict__ b1) {
    extern __shared__ char smem[];
    const uint32_t smb = smem_u32(smem);
    const int tid = threadIdx.x, lane = tid & 31, wid = tid >> 5;
    const int warp_m = wid >> 2, warp_n = wid & 3;
    const int jBase = blockIdx.x * 128;
    const int mBase = blockIdx.y * 128;

    float acc[4][4][4];
#pragma unroll
    for (int i = 0; i < 4; i++)
#pragma unroll
        for (int j = 0; j < 4; j++)
#pragma unroll
            for (int k = 0; k < 4; k++) acc[i][j][k] = 0.f;

    gemm_core<FEAT_I>((const char*)(g_xb + (size_t)mBase * K3_1),
                      (const char*)(g_w1b + (size_t)jBase * K3_1), tid, smb, acc);

    // bias + relu in place
    float bv[4][2];
#pragma unroll
    for (int in = 0; in < 4; in++)
#pragma unroll
        for (int e = 0; e < 2; e++)
            bv[in][e] = __ldg(&b1[jBase + warp_n * 32 + in * 8 + (lane & 3) * 2 + e]);
#pragma unroll
    for (int im = 0; im < 4; im++)
#pragma unroll
        for (int in = 0; in < 4; in++)
#pragma unroll
            for (int q = 0; q < 4; q++) {
                float z = acc[im][in][q] + bv[in][q & 1];
                acc[im][in][q] = z > 0.f ? z : 0.f;
            }

    // 3 planes: peel bf16, stage in smem [128][128] bf16, coalesced copy-out
    __nv_bfloat16* stage = (__nv_bfloat16*)smem;
#pragma unroll
    for (int p = 0; p < 3; p++) {
#pragma unroll
        for (int im = 0; im < 4; im++)
#pragma unroll
            for (int in = 0; in < 4; in++)
#pragma unroll
                for (int rr = 0; rr < 2; rr++) {
                    const int r = warp_m * 64 + im * 16 + (lane >> 2) + rr * 8;
                    const int col = warp_n * 32 + in * 8 + (lane & 3) * 2;
                    __nv_bfloat162 v;
#pragma unroll
                    for (int e = 0; e < 2; e++) {
                        float z = acc[im][in][rr * 2 + e];
                        __nv_bfloat16 hp = __float2bfloat16(z);
                        acc[im][in][rr * 2 + e] = z - __bfloat162float(hp);
                        ((__nv_bfloat16*)&v)[e] = hp;
                    }
                    *(__nv_bfloat162*)&stage[r * 128 + col] = v;
                }
        __syncthreads();
#pragma unroll
        for (int i = 0; i < 8; i++) {
            const int id = tid + 256 * i;          // 2048 float4
            const int r = id >> 4, c4 = id & 15;
            float4 v = *(const float4*)&stage[r * 128 + c4 * 8];
            *(float4*)&g_hb[(size_t)(mBase + r) * K3_2 + p * H_DIM + jBase + c4 * 8] = v;
        }
        __syncthreads();
    }
}

// ---------------------------------------------------------------------------
// GEMM2: logits = h@W2 + b2 + gumbel -> g_logits (fp32)
// ---------------------------------------------------------------------------
__global__ __launch_bounds__(256, 2)
void gemm2_mma(const float* __restrict__ b2, const float* __restrict__ gumbel_u) {
    extern __shared__ char smem[];
    const uint32_t smb = smem_u32(smem);
    const int tid = threadIdx.x, lane = tid & 31, wid = tid >> 5;
    const int warp_m = wid >> 2, warp_n = wid & 3;
    const int jBase = blockIdx.x * 128;
    const int mBase = blockIdx.y * 128;

    float acc[4][4][4];
#pragma unroll
    for (int i = 0; i < 4; i++)
#pragma unroll
        for (int j = 0; j < 4; j++)
#pragma unroll
            for (int k = 0; k < 4; k++) acc[i][j][k] = 0.f;

    gemm_core<H_DIM>((const char*)(g_hb + (size_t)mBase * K3_2),
                     (const char*)(g_w2b + (size_t)jBase * K3_2), tid, smb, acc);

    float bv[4][2];
#pragma unroll
    for (int in = 0; in < 4; in++)
#pragma unroll
        for (int e = 0; e < 2; e++)
            bv[in][e] = __ldg(&b2[jBase + warp_n * 32 + in * 8 + (lane & 3) * 2 + e]);

#pragma unroll
    for (int im = 0; im < 4; im++)
#pragma unroll
        for (int in = 0; in < 4; in++)
#pragma unroll
            for (int rr = 0; rr < 2; rr++) {
                const int m = mBase + warp_m * 64 + im * 16 + (lane >> 2) + rr * 8;
                const int j = jBase + warp_n * 32 + in * 8 + (lane & 3) * 2;
                const float2 u = *(const float2*)&gumbel_u[(size_t)m * CODE + j];
                float2 o;
                o.x = acc[im][in][rr * 2 + 0] + bv[in][0]
                      - logf(-logf(u.x + 1e-10f) + 1e-10f);
                o.y = acc[im][in][rr * 2 + 1] + bv[in][1]
                      - logf(-logf(u.y + 1e-10f) + 1e-10f);
                *(float2*)&g_logits[(size_t)m * CODE + j] = o;
            }
}

// ---------------------------------------------------------------------------
// Conversion kernels (tiled transpose + 3-plane split)
// ---------------------------------------------------------------------------
__global__ __launch_bounds__(256)
void conv_x_kernel(const float* __restrict__ series) {
    __shared__ float s[32][33];
    const int k0 = blockIdx.x * 32, t0 = blockIdx.y * 32, b = blockIdx.z;
    const int tx = threadIdx.x, ty = threadIdx.y;
#pragma unroll
    for (int i = 0; i < 4; i++) {
        int kk = ty + 8 * i;
        s[kk][tx] = series[((size_t)b * FEAT_I + k0 + kk) * T_ + t0 + tx];
    }
    __syncthreads();
#pragma unroll
    for (int i = 0; i < 4; i++) {
        int tt = ty + 8 * i;
        int m = b * T_ + t0 + tt;
        float v = s[tx][tt];
        __nv_bfloat16 h, md, l;
        split3(v, h, md, l);
        __nv_bfloat16* row = g_xb + (size_t)m * K3_1;
        row[0 * FEAT_I + k0 + tx] = h;
        row[1 * FEAT_I + k0 + tx] = md;
        row[2 * FEAT_I + k0 + tx] = l;
    }
}

__global__ __launch_bounds__(256)
void conv_w1_kernel(const float* __restrict__ W1) {
    __shared__ float s[32][33];
    const int k0 = blockIdx.x * 32, n0 = blockIdx.y * 32;
    const int tx = threadIdx.x, ty = threadIdx.y;
#pragma unroll
    for (int i = 0; i < 4; i++) {
        int kk = ty + 8 * i;
        s[kk][tx] = W1[(size_t)(k0 + kk) * H_DIM + n0 + tx];
    }
    __syncthreads();
#pragma unroll
    for (int i = 0; i < 4; i++) {
        int nn = ty + 8 * i;
        float v = s[tx][nn];
        __nv_bfloat16 h, md, l;
        split3(v, h, md, l);
        __nv_bfloat16* row = g_w1b + (size_t)(n0 + nn) * K3_1;
        row[0 * FEAT_I + k0 + tx] = h;
        row[1 * FEAT_I + k0 + tx] = md;
        row[2 * FEAT_I + k0 + tx] = l;
    }
}

__global__ __launch_bounds__(256)
void conv_w2_kernel(const float* __restrict__ W2) {
    __shared__ float s[32][33];
    const int k0 = blockIdx.x * 32, n0 = blockIdx.y * 32;
    const int tx = threadIdx.x, ty = threadIdx.y;
#pragma unroll
    for (int i = 0; i < 4; i++) {
        int kk = ty + 8 * i;
        s[kk][tx] = W2[(size_t)(k0 + kk) * CODE + n0 + tx];
    }
    __syncthreads();
#pragma unroll
    for (int i = 0; i < 4; i++) {
        int nn = ty + 8 * i;
        float v = s[tx][nn];
        __nv_bfloat16 h, md, l;
        split3(v, h, md, l);
        __nv_bfloat16* row = g_w2b + (size_t)(n0 + nn) * K3_2;
        row[0 * H_DIM + k0 + tx] = h;
        row[1 * H_DIM + k0 + tx] = md;
        row[2 * H_DIM + k0 + tx] = l;
    }
}

// ---------------------------------------------------------------------------
// Argmax over 320 perturbed logits per (n,g) + codebook gather (t-coalesced)
// ---------------------------------------------------------------------------
__global__ __launch_bounds__(256)
void argmax_gather_kernel(const float* __restrict__ codebook,
                          float* __restrict__ out)
{
    const int t0 = blockIdx.x * 32;
    const int b  = blockIdx.y;
    const int g  = blockIdx.z;

    __shared__ int s_idx[32];

    const int tid  = threadIdx.x;
    const int lane = tid & 31;
    const int w    = tid >> 5;

#pragma unroll
    for (int rr = 0; rr < 4; rr++) {
        const int tl = w * 4 + rr;
        const int n  = b * T_ + t0 + tl;
        const float* lp = g_logits + (size_t)n * CODE + g * CODE_G;
        float best = -INFINITY;
        int   bi   = 0;
        for (int c = lane; c < CODE_G; c += 32) {
            float v = lp[c];
            if (v > best) { best = v; bi = c; }
        }
#pragma unroll
        for (int off = 16; off; off >>= 1) {
            float ov = __shfl_down_sync(0xffffffffu, best, off);
            int   oi = __shfl_down_sync(0xffffffffu, bi,   off);
            if (ov > best || (ov == best && oi < bi)) { best = ov; bi = oi; }
        }
        if (lane == 0) {
            s_idx[tl] = bi;
            out[Q_ELEMS + (size_t)n * 2 + g] = (float)bi;
        }
    }
    __syncthreads();

    const int tx  = tid & 31;
    const int fy  = tid >> 5;
    const int idx = s_idx[tx];
    const float* cbrow = codebook + ((size_t)g * CODE_G + idx) * FEAT_G;
    float* outb = out + ((size_t)b * 512 + g * FEAT_G) * T_ + t0;
    for (int f = fy; f < FEAT_G; f += 8)
        outb[(size_t)f * T_ + tx] = cbrow[f];
}

// ---------------------------------------------------------------------------
extern "C" void kernel_launch(void* const* d_in, const int* in_sizes, int n_in,
                              void* d_out, int out_size)
{
    const float* series   = (const float*)d_in[0];
    const float* gumbel_u = (const float*)d_in[1];
    const float* W1       = (const float*)d_in[2];
    const float* b1       = (const float*)d_in[3];
    const float* W2       = (const float*)d_in[4];
    const float* b2       = (const float*)d_in[5];
    const float* codebook = (const float*)d_in[6];
    float* out = (float*)d_out;

    cudaFuncSetAttribute(gemm1_mma, cudaFuncAttributeMaxDynamicSharedMemorySize, SMEM_DYN);
    cudaFuncSetAttribute(gemm2_mma, cudaFuncAttributeMaxDynamicSharedMemorySize, SMEM_DYN);

    conv_x_kernel <<<dim3(FEAT_I / 32, T_ / 32, B_), dim3(32, 8)>>>(series);
    conv_w1_kernel<<<dim3(FEAT_I / 32, H_DIM / 32),  dim3(32, 8)>>>(W1);
    conv_w2_kernel<<<dim3(H_DIM / 32, CODE / 32),    dim3(32, 8)>>>(W2);

    gemm1_mma<<<dim3(H_DIM / 128, N_ / 128), 256, SMEM_DYN>>>(b1);
    gemm2_mma<<<dim3(CODE / 128,  N_ / 128), 256, SMEM_DYN>>>(b2, gumbel_u);

    argmax_gather_kernel<<<dim3(T_ / 32, B_, 2), 256>>>(codebook, out);
}

// round 10
// speedup vs baseline: 1.7717x; 1.7053x over previous
#include <cuda_runtime.h>
#include <cuda_fp16.h>
#include <math.h>
#include <stdint.h>

#define FEAT_I 512
#define H_DIM  1024
#define CODE   640
#define CODE_G 320
#define FEAT_G 256
#define B_     8
#define T_     4096
#define N_     (B_ * T_)                  // 32768
#define Q_ELEMS ((size_t)B_ * 512 * T_)   // 16,777,216

#define K2_1 (2 * FEAT_I)    // 1024
#define K2_2 (2 * H_DIM)     // 2048

// W pre-scale (exact power of 2) keeps fp16 lo-planes out of denormal range
#define WSCALE    64.0f
#define INV_WSCALE (1.0f / 64.0f)

// dynamic smem: 2 bufs x (2 A-planes + 2 B-planes) x 8KB = 64KB per CTA
#define PLANE_SZ   8192
#define B_OFF      16384
#define BUF_STRIDE 32768
#define SMEM_DYN   65536

// ---------------------------------------------------------------------------
// Device scratch (allocation-free rule)
// ---------------------------------------------------------------------------
__device__ __half g_xh [(size_t)N_    * K2_1];  // x planes    [m][p*512+k]
__device__ __half g_w1h[(size_t)H_DIM * K2_1];  // (64*W1)^T   [n][p*512+k]
__device__ __half g_hh [(size_t)N_    * K2_2];  // h planes    [m][p*1024+k]
__device__ __half g_w2h[(size_t)CODE  * K2_2];  // (64*W2)^T   [n][p*1024+k]
__device__ float  g_logits[(size_t)N_ * CODE];  // perturbed logits

// ---------------------------------------------------------------------------
// PTX helpers (arch-agnostic sm_80-class)
// ---------------------------------------------------------------------------
__device__ __forceinline__ uint32_t smem_u32(const void* p) {
    uint32_t a;
    asm("{ .reg .u64 t; cvta.to.shared.u64 t, %1; cvt.u32.u64 %0, t; }" : "=r"(a) : "l"(p));
    return a;
}
__device__ __forceinline__ void cp16(uint32_t saddr, const void* g) {
    asm volatile("cp.async.cg.shared.global [%0], [%1], 16;" :: "r"(saddr), "l"(g));
}
#define CP_COMMIT() asm volatile("cp.async.commit_group;" ::: "memory")
#define CP_WAIT0()  asm volatile("cp.async.wait_group 0;" ::: "memory")
#define CP_WAIT1()  asm volatile("cp.async.wait_group 1;" ::: "memory")

__device__ __forceinline__ void ldsm4(uint32_t& a, uint32_t& b, uint32_t& c, uint32_t& d,
                                      uint32_t addr) {
    asm volatile("ldmatrix.sync.aligned.m8n8.x4.shared.b16 {%0,%1,%2,%3}, [%4];"
                 : "=r"(a), "=r"(b), "=r"(c), "=r"(d) : "r"(addr));
}
__device__ __forceinline__ void mma16816(float* d, const uint32_t* a, uint32_t b0, uint32_t b1) {
    asm volatile("mma.sync.aligned.m16n8k16.row.col.f32.f16.f16.f32 "
                 "{%0,%1,%2,%3},{%4,%5,%6,%7},{%8,%9},{%0,%1,%2,%3};"
                 : "+f"(d[0]), "+f"(d[1]), "+f"(d[2]), "+f"(d[3])
                 : "r"(a[0]), "r"(a[1]), "r"(a[2]), "r"(a[3]), "r"(b0), "r"(b1));
}

// fp32 -> 2x fp16 split (exact to ~2^-24 for normal-range values)
__device__ __forceinline__ void split2(float v, __half& hi, __half& lo) {
    hi = __float2half_rn(v);
    lo = __float2half_rn(v - __half2float(hi));
}

// swizzled byte offset within one 128x64B plane
__device__ __forceinline__ uint32_t plane_swz(int r, int c) {
    return (uint32_t)(r * 64 + ((c ^ ((r >> 1) & 3)) * 16));
}

// ---------------------------------------------------------------------------
// Core: 128x128 block. Super-chunk = 32 k-columns of all 4 planes (32KB).
// 3 cross terms: A0*B0, A0*B1, A1*B0. A-plane-outer order keeps 1 A-frag +
// 1 B-frag set live (~128 regs => 2 CTAs/SM). 14 ldsm feed 48 HMMA per k16.
// ---------------------------------------------------------------------------
template<int KPLANE>
__device__ __forceinline__ void gemm_core(const char* __restrict__ Abase,
                                          const char* __restrict__ Bbase,
                                          int tid, uint32_t smb,
                                          float acc[4][4][4]) {
    const int lane = tid & 31, wid = tid >> 5;
    const int warp_m = wid >> 2;     // 0..1
    const int warp_n = wid & 3;      // 0..3
    constexpr int KCH = KPLANE / 32;
    const size_t ROWB = (size_t)KPLANE * 4;   // 2 planes * 2 bytes

    const int cst = tid & 3;         // 16B chunk for stores
    const int rst = tid >> 2;        // 0..63

    auto issue = [&](int kc, int buf) {
        const uint32_t base = smb + buf * BUF_STRIDE;
#pragma unroll
        for (int p = 0; p < 2; p++) {
            const size_t col = (size_t)(p * KPLANE + kc * 32) * 2 + cst * 16;
#pragma unroll
            for (int i = 0; i < 2; i++) {
                const int r = rst + 64 * i;
                const uint32_t so = plane_swz(r, cst);
                cp16(base + p * PLANE_SZ + so,         Abase + (size_t)r * ROWB + col);
                cp16(base + B_OFF + p * PLANE_SZ + so, Bbase + (size_t)r * ROWB + col);
            }
        }
    };

    issue(0, 0); CP_COMMIT();
    issue(1, 1); CP_COMMIT();

    for (int kc = 0; kc < KCH; kc++) {
        if (kc == KCH - 1) { CP_WAIT0(); } else { CP_WAIT1(); }
        __syncthreads();
        const uint32_t bufb = smb + (kc & 1) * BUF_STRIDE;
#pragma unroll
        for (int kk = 0; kk < 2; kk++) {
            const int lrow = lane & 15;
            const int ch = kk * 2 + (lane >> 4);
            uint32_t afr[4][4], bfr[2][4];

            auto loadA = [&](int pa) {
                const uint32_t bA = bufb + pa * PLANE_SZ;
#pragma unroll
                for (int im = 0; im < 4; im++) {
                    const int r = warp_m * 64 + im * 16 + lrow;
                    ldsm4(afr[im][0], afr[im][1], afr[im][2], afr[im][3],
                          bA + plane_swz(r, ch));
                }
            };
            auto loadB = [&](int pb) {
                const uint32_t bB = bufb + B_OFF + pb * PLANE_SZ;
#pragma unroll
                for (int i2 = 0; i2 < 2; i2++) {
                    const int r = warp_n * 32 + i2 * 16 + lrow;
                    ldsm4(bfr[i2][0], bfr[i2][1], bfr[i2][2], bfr[i2][3],
                          bB + plane_swz(r, ch));
                }
            };
            auto mmas = [&]() {
#pragma unroll
                for (int im = 0; im < 4; im++)
#pragma unroll
                    for (int in = 0; in < 4; in++)
                        mma16816(acc[im][in], afr[im],
                                 bfr[in >> 1][in & 1], bfr[in >> 1][(in & 1) + 2]);
            };

            loadA(0); loadB(0); mmas(); loadB(1); mmas();
            loadA(1); loadB(0); mmas();
        }
        __syncthreads();
        if (kc + 2 < KCH) { issue(kc + 2, kc & 1); CP_COMMIT(); }
    }
    __syncthreads();
}

// ---------------------------------------------------------------------------
// GEMM1: h = relu((x @ 64*W1)/64 + b1) -> split2 -> g_hh (smem-staged stores)
// ---------------------------------------------------------------------------
__global__ __launch_bounds__(256, 2)
void gemm1_mma(const float* __restrict__ b1) {
    extern __shared__ char smem[];
    const uint32_t smb = smem_u32(smem);
    const int tid = threadIdx.x, lane = tid & 31, wid = tid >> 5;
    const int warp_m = wid >> 2, warp_n = wid & 3;
    const int jBase = blockIdx.x * 128;
    const int mBase = blockIdx.y * 128;

    float acc[4][4][4];
#pragma unroll
    for (int i = 0; i < 4; i++)
#pragma unroll
        for (int j = 0; j < 4; j++)
#pragma unroll
            for (int k = 0; k < 4; k++) acc[i][j][k] = 0.f;

    gemm_core<FEAT_I>((const char*)(g_xh + (size_t)mBase * K2_1),
                      (const char*)(g_w1h + (size_t)jBase * K2_1), tid, smb, acc);

    // scale back, bias, relu in place
    float bv[4][2];
#pragma unroll
    for (int in = 0; in < 4; in++)
#pragma unroll
        for (int e = 0; e < 2; e++)
            bv[in][e] = __ldg(&b1[jBase + warp_n * 32 + in * 8 + (lane & 3) * 2 + e]);
#pragma unroll
    for (int im = 0; im < 4; im++)
#pragma unroll
        for (int in = 0; in < 4; in++)
#pragma unroll
            for (int q = 0; q < 4; q++) {
                float z = acc[im][in][q] * INV_WSCALE + bv[in][q & 1];
                acc[im][in][q] = z > 0.f ? z : 0.f;
            }

    // 2 planes: peel fp16, stage in smem [128][128] half, coalesced copy-out
    __half* stage = (__half*)smem;
#pragma unroll
    for (int p = 0; p < 2; p++) {
#pragma unroll
        for (int im = 0; im < 4; im++)
#pragma unroll
            for (int in = 0; in < 4; in++)
#pragma unroll
                for (int rr = 0; rr < 2; rr++) {
                    const int r = warp_m * 64 + im * 16 + (lane >> 2) + rr * 8;
                    const int col = warp_n * 32 + in * 8 + (lane & 3) * 2;
                    __half2 v;
#pragma unroll
                    for (int e = 0; e < 2; e++) {
                        float z = acc[im][in][rr * 2 + e];
                        __half hp = __float2half_rn(z);
                        acc[im][in][rr * 2 + e] = z - __half2float(hp);
                        ((__half*)&v)[e] = hp;
                    }
                    *(__half2*)&stage[r * 128 + col] = v;
                }
        __syncthreads();
#pragma unroll
        for (int i = 0; i < 8; i++) {
            const int id = tid + 256 * i;          // 2048 float4
            const int r = id >> 4, c4 = id & 15;
            float4 v = *(const float4*)&stage[r * 128 + c4 * 8];
            *(float4*)&g_hh[(size_t)(mBase + r) * K2_2 + p * H_DIM + jBase + c4 * 8] = v;
        }
        __syncthreads();
    }
}

// ---------------------------------------------------------------------------
// GEMM2: logits = (h @ 64*W2)/64 + b2 + gumbel -> g_logits (fp32)
// ---------------------------------------------------------------------------
__global__ __launch_bounds__(256, 2)
void gemm2_mma(const float* __restrict__ b2, const float* __restrict__ gumbel_u) {
    extern __shared__ char smem[];
    const uint32_t smb = smem_u32(smem);
    const int tid = threadIdx.x, lane = tid & 31, wid = tid >> 5;
    const int warp_m = wid >> 2, warp_n = wid & 3;
    const int jBase = blockIdx.x * 128;
    const int mBase = blockIdx.y * 128;

    float acc[4][4][4];
#pragma unroll
    for (int i = 0; i < 4; i++)
#pragma unroll
        for (int j = 0; j < 4; j++)
#pragma unroll
            for (int k = 0; k < 4; k++) acc[i][j][k] = 0.f;

    gemm_core<H_DIM>((const char*)(g_hh + (size_t)mBase * K2_2),
                     (const char*)(g_w2h + (size_t)jBase * K2_2), tid, smb, acc);

    float bv[4][2];
#pragma unroll
    for (int in = 0; in < 4; in++)
#pragma unroll
        for (int e = 0; e < 2; e++)
            bv[in][e] = __ldg(&b2[jBase + warp_n * 32 + in * 8 + (lane & 3) * 2 + e]);

#pragma unroll
    for (int im = 0; im < 4; im++)
#pragma unroll
        for (int in = 0; in < 4; in++)
#pragma unroll
            for (int rr = 0; rr < 2; rr++) {
                const int m = mBase + warp_m * 64 + im * 16 + (lane >> 2) + rr * 8;
                const int j = jBase + warp_n * 32 + in * 8 + (lane & 3) * 2;
                const float2 u = *(const float2*)&gumbel_u[(size_t)m * CODE + j];
                float2 o;
                o.x = acc[im][in][rr * 2 + 0] * INV_WSCALE + bv[in][0]
                      - logf(-logf(u.x + 1e-10f) + 1e-10f);
                o.y = acc[im][in][rr * 2 + 1] * INV_WSCALE + bv[in][1]
                      - logf(-logf(u.y + 1e-10f) + 1e-10f);
                *(float2*)&g_logits[(size_t)m * CODE + j] = o;
            }
}

// ---------------------------------------------------------------------------
// Conversion kernels (tiled transpose + 2-plane fp16 split)
// ---------------------------------------------------------------------------
__global__ __launch_bounds__(256)
void conv_x_kernel(const float* __restrict__ series) {
    __shared__ float s[32][33];
    const int k0 = blockIdx.x * 32, t0 = blockIdx.y * 32, b = blockIdx.z;
    const int tx = threadIdx.x, ty = threadIdx.y;
#pragma unroll
    for (int i = 0; i < 4; i++) {
        int kk = ty + 8 * i;
        s[kk][tx] = series[((size_t)b * FEAT_I + k0 + kk) * T_ + t0 + tx];
    }
    __syncthreads();
#pragma unroll
    for (int i = 0; i < 4; i++) {
        int tt = ty + 8 * i;
        int m = b * T_ + t0 + tt;
        __half hi, lo;
        split2(s[tx][tt], hi, lo);
        __half* row = g_xh + (size_t)m * K2_1;
        row[0 * FEAT_I + k0 + tx] = hi;
        row[1 * FEAT_I + k0 + tx] = lo;
    }
}

__global__ __launch_bounds__(256)
void conv_w1_kernel(const float* __restrict__ W1) {
    __shared__ float s[32][33];
    const int k0 = blockIdx.x * 32, n0 = blockIdx.y * 32;
    const int tx = threadIdx.x, ty = threadIdx.y;
#pragma unroll
    for (int i = 0; i < 4; i++) {
        int kk = ty + 8 * i;
        s[kk][tx] = W1[(size_t)(k0 + kk) * H_DIM + n0 + tx];
    }
    __syncthreads();
#pragma unroll
    for (int i = 0; i < 4; i++) {
        int nn = ty + 8 * i;
        __half hi, lo;
        split2(s[tx][nn] * WSCALE, hi, lo);
        __half* row = g_w1h + (size_t)(n0 + nn) * K2_1;
        row[0 * FEAT_I + k0 + tx] = hi;
        row[1 * FEAT_I + k0 + tx] = lo;
    }
}

__global__ __launch_bounds__(256)
void conv_w2_kernel(const float* __restrict__ W2) {
    __shared__ float s[32][33];
    const int k0 = blockIdx.x * 32, n0 = blockIdx.y * 32;
    const int tx = threadIdx.x, ty = threadIdx.y;
#pragma unroll
    for (int i = 0; i < 4; i++) {
        int kk = ty + 8 * i;
        s[kk][tx] = W2[(size_t)(k0 + kk) * CODE + n0 + tx];
    }
    __syncthreads();
#pragma unroll
    for (int i = 0; i < 4; i++) {
        int nn = ty + 8 * i;
        __half hi, lo;
        split2(s[tx][nn] * WSCALE, hi, lo);
        __half* row = g_w2h + (size_t)(n0 + nn) * K2_2;
        row[0 * H_DIM + k0 + tx] = hi;
        row[1 * H_DIM + k0 + tx] = lo;
    }
}

// ---------------------------------------------------------------------------
// Argmax over 320 perturbed logits per (n,g) + codebook gather (t-coalesced)
// ---------------------------------------------------------------------------
__global__ __launch_bounds__(256)
void argmax_gather_kernel(const float* __restrict__ codebook,
                          float* __restrict__ out)
{
    const int t0 = blockIdx.x * 32;
    const int b  = blockIdx.y;
    const int g  = blockIdx.z;

    __shared__ int s_idx[32];

    const int tid  = threadIdx.x;
    const int lane = tid & 31;
    const int w    = tid >> 5;

#pragma unroll
    for (int rr = 0; rr < 4; rr++) {
        const int tl = w * 4 + rr;
        const int n  = b * T_ + t0 + tl;
        const float* lp = g_logits + (size_t)n * CODE + g * CODE_G;
        float best = -INFINITY;
        int   bi   = 0;
        for (int c = lane; c < CODE_G; c += 32) {
            float v = lp[c];
            if (v > best) { best = v; bi = c; }
        }
#pragma unroll
        for (int off = 16; off; off >>= 1) {
            float ov = __shfl_down_sync(0xffffffffu, best, off);
            int   oi = __shfl_down_sync(0xffffffffu, bi,   off);
            if (ov > best || (ov == best && oi < bi)) { best = ov; bi = oi; }
        }
        if (lane == 0) {
            s_idx[tl] = bi;
            out[Q_ELEMS + (size_t)n * 2 + g] = (float)bi;
        }
    }
    __syncthreads();

    const int tx  = tid & 31;
    const int fy  = tid >> 5;
    const int idx = s_idx[tx];
    const float* cbrow = codebook + ((size_t)g * CODE_G + idx) * FEAT_G;
    float* outb = out + ((size_t)b * 512 + g * FEAT_G) * T_ + t0;
    for (int f = fy; f < FEAT_G; f += 8)
        outb[(size_t)f * T_ + tx] = cbrow[f];
}

// ---------------------------------------------------------------------------
extern "C" void kernel_launch(void* const* d_in, const int* in_sizes, int n_in,
                              void* d_out, int out_size)
{
    const float* series   = (const float*)d_in[0];
    const float* gumbel_u = (const float*)d_in[1];
    const float* W1       = (const float*)d_in[2];
    const float* b1       = (const float*)d_in[3];
    const float* W2       = (const float*)d_in[4];
    const float* b2       = (const float*)d_in[5];
    const float* codebook = (const float*)d_in[6];
    float* out = (float*)d_out;

    cudaFuncSetAttribute(gemm1_mma, cudaFuncAttributeMaxDynamicSharedMemorySize, SMEM_DYN);
    cudaFuncSetAttribute(gemm2_mma, cudaFuncAttributeMaxDynamicSharedMemorySize, SMEM_DYN);

    conv_x_kernel <<<dim3(FEAT_I / 32, T_ / 32, B_), dim3(32, 8)>>>(series);
    conv_w1_kernel<<<dim3(FEAT_I / 32, H_DIM / 32),  dim3(32, 8)>>>(W1);
    conv_w2_kernel<<<dim3(H_DIM / 32, CODE / 32),    dim3(32, 8)>>>(W2);

    gemm1_mma<<<dim3(H_DIM / 128, N_ / 128), 256, SMEM_DYN>>>(b1);
    gemm2_mma<<<dim3(CODE / 128,  N_ / 128), 256, SMEM_DYN>>>(b2, gumbel_u);

    argmax_gather_kernel<<<dim3(T_ / 32, B_, 2), 256>>>(codebook, out);
}